// round 14
// baseline (speedup 1.0000x reference)
#include <cuda_runtime.h>
#include <cuda_fp16.h>
#include <cstdint>

#define S        4096
#define D_IN     128
#define H        4
#define D        32
#define HD       128
#define KSPLIT   4
#define KEYS_PER_SPLIT (S / KSPLIT)   // 1024
#define KT       128                   // keys per smem tile
#define QT       256                   // queries per attention block (8 warps * 32)
#define NEGBIG   1e30f
#define QSCALE   (0.17677669529663687f * 1.4426950408889634f)  // scale*log2e

#define V_CHSTR  264                   // dwords per 16-key V chunk (256 + 8 pad)

// ---------------- scratch (fp16x2 packed) ------------------------------------
__device__ uint32_t g_q[H * S * 16];        // permuted cols, pre-scaled by QSCALE
__device__ uint32_t g_k[H * S * 16];        // permuted cols
__device__ uint32_t g_v[H * S * 16];        // plain d-pair packing
__device__ uint32_t g_xf[S * 64];           // x packed, A-fragment order
__device__ uint32_t g_wt[3 * 128 * 64];     // W^T packed, swizzled smem image
__device__ float g_pl[H * S * KSPLIT];
__device__ uint32_t g_po[H * S * KSPLIT * 16];   // fp16x2 partial outputs (d-pairs)

// ---------------- helpers ----------------------------------------------------
__device__ __forceinline__ float ex2(float x) {
    float r;
    asm("ex2.approx.f32 %0, %1;" : "=f"(r) : "f"(x));
    return r;
}
__device__ __forceinline__ uint32_t pack_h2(float lo, float hi) {
    __half2 h = __floats2half2_rn(lo, hi);       // x = lo bits, y = hi bits
    return *reinterpret_cast<uint32_t*>(&h);
}
__device__ __forceinline__ float2 unpack_h2(uint32_t u) {
    __half2 h = *reinterpret_cast<__half2*>(&u);
    return __half22float2(h);
}
__device__ __forceinline__ void mma16(float* d,
                                      uint32_t a0, uint32_t a1, uint32_t a2, uint32_t a3,
                                      uint32_t b0, uint32_t b1) {
    asm("mma.sync.aligned.m16n8k16.row.col.f32.f16.f16.f32 "
        "{%0,%1,%2,%3}, {%4,%5,%6,%7}, {%8,%9}, {%0,%1,%2,%3};"
        : "+f"(d[0]), "+f"(d[1]), "+f"(d[2]), "+f"(d[3])
        : "r"(a0), "r"(a1), "r"(a2), "r"(a3), "r"(b0), "r"(b1));
}
// group swizzle keyed on row (bit0 -> group bit2; bits1-2 -> group bits0-1)
__device__ __forceinline__ int swz3(int r) { return ((r & 1) << 2) | ((r >> 1) & 3); }

// ---------------- kernel 0: prep (pack x in A-frag order; pack W^T) ----------
// grid 304: blocks 0..255 pack x (4 pairs/thread); 256..303 pack W (2 pairs/thread).
__global__ __launch_bounds__(256) void prep_kernel(
    const float* __restrict__ x,
    const float* __restrict__ Wq, const float* __restrict__ Wk,
    const float* __restrict__ Wv) {
    const int bid = blockIdx.x;
    const int tid = threadIdx.x;
    if (bid < 256) {
        const int base = (bid * 256 + tid) * 4;
        #pragma unroll
        for (int i = 0; i < 4; i++) {
            int e = base + i;                 // pair index 0..262143
            int row = e >> 6, p = e & 63;
            float2 xv = *(const float2*)(x + (size_t)row * D_IN + 2 * p);
            g_xf[row * 64 + ((p & 7) << 3) + (p >> 3)] = pack_h2(xv.x, xv.y);
        }
    } else {
        const int b = bid - 256;              // 0..47
        const int proj = b >> 4, chunk = b & 15;
        const float* W = (proj == 0) ? Wq : (proj == 1) ? Wk : Wv;
        uint32_t* out = g_wt + proj * 8192;
        #pragma unroll
        for (int i = 0; i < 2; i++) {
            int e = chunk * 512 + i * 256 + tid;
            int n = e & 127, p = e >> 7;
            float w0 = W[(size_t)(2 * p) * HD + n];
            float w1 = W[(size_t)(2 * p + 1) * HD + n];
            out[n * 64 + ((((p & 7) ^ swz3(n)) << 3) | (p >> 3))] = pack_h2(w0, w1);
        }
    }
}

// ---------------- kernel 1: fp16 MMA QKV projection (prepped inputs) ---------
// grid (64 row-tiles of 64 rows, 3 proj) = 192 blocks; 256 threads = 8 warps.
__global__ __launch_bounds__(256) void proj_kernel(
    const float* __restrict__ bq, const float* __restrict__ bk,
    const float* __restrict__ bv) {

    __shared__ __align__(16) uint32_t swt[8192];   // 32 KB W^T image
    __shared__ float sb[128];

    const int rowbase = blockIdx.x * 64;
    const int proj = blockIdx.y;
    const float* bias = (proj == 0) ? bq : (proj == 1) ? bk : bv;
    uint32_t* out     = (proj == 0) ? g_q : (proj == 1) ? g_k : g_v;

    const int tid  = threadIdx.x;
    const int wid  = tid >> 5;
    const int lane = tid & 31;
    const int gid  = lane >> 2;
    const int tig  = lane & 3;
    const int nh   = wid >> 2;
    const int rh   = wid & 3;

    {
        const uint4* src = (const uint4*)(g_wt + proj * 8192);
        uint4* dst = (uint4*)swt;
        #pragma unroll
        for (int i = 0; i < 8; i++) dst[tid + i * 256] = src[tid + i * 256];
    }
    if (tid < 128) sb[tid] = bias[tid];

    const int r0 = rowbase + rh * 16 + gid;
    const int r1 = r0 + 8;
    uint32_t a0[8], a1[8], a2[8], a3[8];
    {
        const uint32_t* x0 = g_xf + (size_t)r0 * 64;
        const uint32_t* x1 = g_xf + (size_t)r1 * 64;
        *(uint4*)&a0[0] = *(const uint4*)&x0[tig * 8];
        *(uint4*)&a0[4] = *(const uint4*)&x0[tig * 8 + 4];
        *(uint4*)&a2[0] = *(const uint4*)&x0[(tig + 4) * 8];
        *(uint4*)&a2[4] = *(const uint4*)&x0[(tig + 4) * 8 + 4];
        *(uint4*)&a1[0] = *(const uint4*)&x1[tig * 8];
        *(uint4*)&a1[4] = *(const uint4*)&x1[tig * 8 + 4];
        *(uint4*)&a3[0] = *(const uint4*)&x1[(tig + 4) * 8];
        *(uint4*)&a3[4] = *(const uint4*)&x1[(tig + 4) * 8 + 4];
    }
    __syncthreads();

    const float oscale = (proj == 0) ? QSCALE : 1.0f;
    const bool permute = (proj != 2);

    #pragma unroll 1
    for (int nb2 = 0; nb2 < 4; nb2++) {
        const int nbA = nh * 8 + 2 * nb2, nbB = nbA + 1;
        const int nA = nbA * 8 + gid, nB = nbB * 8 + gid;

        uint32_t b0A[8], b1A[8], b0B[8], b1B[8];
        {
            const uint32_t* wA = &swt[nA * 64];
            int ga = ((tig)     ^ swz3(nA)) << 3;
            int gb = ((tig + 4) ^ swz3(nA)) << 3;
            *(uint4*)&b0A[0] = *(const uint4*)&wA[ga]; *(uint4*)&b0A[4] = *(const uint4*)&wA[ga + 4];
            *(uint4*)&b1A[0] = *(const uint4*)&wA[gb]; *(uint4*)&b1A[4] = *(const uint4*)&wA[gb + 4];
            const uint32_t* wB = &swt[nB * 64];
            int gc = ((tig)     ^ swz3(nB)) << 3;
            int gd = ((tig + 4) ^ swz3(nB)) << 3;
            *(uint4*)&b0B[0] = *(const uint4*)&wB[gc]; *(uint4*)&b0B[4] = *(const uint4*)&wB[gc + 4];
            *(uint4*)&b1B[0] = *(const uint4*)&wB[gd]; *(uint4*)&b1B[4] = *(const uint4*)&wB[gd + 4];
        }

        float cA[4] = {0.f, 0.f, 0.f, 0.f};
        float cB[4] = {0.f, 0.f, 0.f, 0.f};
        #pragma unroll
        for (int ks = 0; ks < 8; ks++) {
            mma16(cA, a0[ks], a1[ks], a2[ks], a3[ks], b0A[ks], b1A[ks]);
            mma16(cB, a0[ks], a1[ks], a2[ks], a3[ks], b0B[ks], b1B[ks]);
        }

        #pragma unroll
        for (int s = 0; s < 2; s++) {
            const float* c = s ? cB : cA;
            const int nb = s ? nbB : nbA;
            const int col0 = 8 * nb + 2 * tig;
            float v0 = (c[0] + sb[col0])     * oscale;
            float v1 = (c[1] + sb[col0 + 1]) * oscale;
            float v2 = (c[2] + sb[col0])     * oscale;
            float v3 = (c[3] + sb[col0 + 1]) * oscale;
            int h0 = col0 >> 5;
            int d2 = (col0 >> 1) & 15;
            int p  = permute ? (((d2 & 3) << 2) | (d2 >> 2)) : d2;
            out[((size_t)h0 * S + r0) * 16 + p] = pack_h2(v0, v1);
            out[((size_t)h0 * S + r1) * 16 + p] = pack_h2(v2, v3);
        }
    }
}

// ---------------- kernel 2: fp16 m16n8k16 flash attention -------------------
// grid (16, H, 4) = 256 blocks; 256 threads = 8 warps; 32 queries per warp.
__global__ __launch_bounds__(256, 2) void attn_kernel(const int* __restrict__ mask) {
    const int qtile = blockIdx.x;
    const int h     = blockIdx.y;
    const int kc    = blockIdx.z;
    const int tid   = threadIdx.x;
    const int warp  = tid >> 5;
    const int lane  = tid & 31;
    const int gid   = lane >> 2;
    const int tig   = lane & 3;

    __shared__ __align__(16) uint32_t sk[KT * 16];             // 8 KB (permuted fp16x2)
    __shared__ __align__(16) uint32_t sv[(KT / 16) * V_CHSTR]; // 8.25 KB
    __shared__ float sbias[KT];
    __shared__ int smask[64];

    if (tid < 64) smask[tid] = mask[tid];

    const int qbase = qtile * QT + warp * 32;

    uint4 qlo[2], qhi[2];
    #pragma unroll
    for (int t = 0; t < 2; t++) {
        const uint32_t* qr = g_q + ((size_t)(h * S) + qbase + t * 16 + gid) * 16;
        qlo[t] = *(const uint4*)(qr + 4 * tig);
        qhi[t] = *(const uint4*)(qr + 8 * 16 + 4 * tig);
    }

    float o[2][4][4];
    #pragma unroll
    for (int t = 0; t < 2; t++)
        #pragma unroll
        for (int nc = 0; nc < 4; nc++)
            #pragma unroll
            for (int r = 0; r < 4; r++) o[t][nc][r] = 0.0f;
    float l[2][2] = {{0.f, 0.f}, {0.f, 0.f}};

    const int kbase = kc * KEYS_PER_SPLIT;
    const float2* sb2 = (const float2*)sbias;

    const int vkey2 = tid & 63;
    const int vdb   = tid >> 6;
    const int vch   = vkey2 >> 3;
    const int vkc2  = vkey2 & 7;
    const int vwoff = vch * V_CHSTR + 64 * vdb + 2 * (vkc2 & 3) + (vkc2 >> 2);

    for (int jt = 0; jt < KEYS_PER_SPLIT / KT; jt++) {   // 8 tiles
        __syncthreads();
        {
            const uint4* kg4 = (const uint4*)(g_k + ((size_t)(h * S) + kbase + jt * KT) * 16);
            ((uint4*)sk)[tid]       = kg4[tid];
            ((uint4*)sk)[tid + 256] = kg4[tid + 256];

            const uint4* vg4 = (const uint4*)(g_v + ((size_t)(h * S) + kbase + jt * KT) * 16);
            uint4 e4 = vg4[(2 * vkey2) * 4 + vdb];
            uint4 o4 = vg4[(2 * vkey2) * 4 + 4 + vdb];
            uint32_t* dst = &sv[vwoff];
            dst[0]  = __byte_perm(e4.x, o4.x, 0x5410);
            dst[8]  = __byte_perm(e4.x, o4.x, 0x7632);
            dst[16] = __byte_perm(e4.y, o4.y, 0x5410);
            dst[24] = __byte_perm(e4.y, o4.y, 0x7632);
            dst[32] = __byte_perm(e4.z, o4.z, 0x5410);
            dst[40] = __byte_perm(e4.z, o4.z, 0x7632);
            dst[48] = __byte_perm(e4.w, o4.w, 0x5410);
            dst[56] = __byte_perm(e4.w, o4.w, 0x7632);

            if (tid < KT) {
                int key = kbase + jt * KT + tid;
                sbias[tid] = (smask[key >> 6] && smask[key & 63]) ? 0.0f : -NEGBIG;
            }
        }
        __syncthreads();

        #pragma unroll 1
        for (int kg = 0; kg < KT / 16; kg++) {     // 8 chunks of 16 keys
            const uint4 kb0 = *(const uint4*)&sk[(kg * 16 + gid) * 16 + 4 * tig];
            const uint4 kb1 = *(const uint4*)&sk[(kg * 16 + 8 + gid) * 16 + 4 * tig];

            float c[2][2][4];
            #pragma unroll
            for (int t = 0; t < 2; t++) {
                #pragma unroll
                for (int g = 0; g < 2; g++)
                    c[t][g][0] = c[t][g][1] = c[t][g][2] = c[t][g][3] = 0.0f;
                mma16(c[t][0], qlo[t].x, qhi[t].x, qlo[t].y, qhi[t].y, kb0.x, kb0.y);
                mma16(c[t][0], qlo[t].z, qhi[t].z, qlo[t].w, qhi[t].w, kb0.z, kb0.w);
                mma16(c[t][1], qlo[t].x, qhi[t].x, qlo[t].y, qhi[t].y, kb1.x, kb1.y);
                mma16(c[t][1], qlo[t].z, qhi[t].z, qlo[t].w, qhi[t].w, kb1.z, kb1.w);
            }

            float2 bg0 = sb2[kg * 8 + tig];
            float2 bg1 = sb2[kg * 8 + 4 + tig];

            uint32_t pa[2][4];
            #pragma unroll
            for (int t = 0; t < 2; t++) {
                float p00 = ex2(c[t][0][0] + bg0.x), p01 = ex2(c[t][0][1] + bg0.y);
                float p02 = ex2(c[t][0][2] + bg0.x), p03 = ex2(c[t][0][3] + bg0.y);
                float p10 = ex2(c[t][1][0] + bg1.x), p11 = ex2(c[t][1][1] + bg1.y);
                float p12 = ex2(c[t][1][2] + bg1.x), p13 = ex2(c[t][1][3] + bg1.y);
                l[t][0] += (p00 + p01) + (p10 + p11);
                l[t][1] += (p02 + p03) + (p12 + p13);
                pa[t][0] = pack_h2(p00, p01);
                pa[t][1] = pack_h2(p02, p03);
                pa[t][2] = pack_h2(p10, p11);
                pa[t][3] = pack_h2(p12, p13);
            }

            const uint32_t* vb = &sv[kg * V_CHSTR + 8 * gid + 2 * tig];
            #pragma unroll
            for (int nc = 0; nc < 4; nc++) {
                uint2 vv = *(const uint2*)(vb + 64 * nc);
                mma16(o[0][nc], pa[0][0], pa[0][1], pa[0][2], pa[0][3], vv.x, vv.y);
                mma16(o[1][nc], pa[1][0], pa[1][1], pa[1][2], pa[1][3], vv.x, vv.y);
            }
        }
    }

    // ---- reduce l within groups; write fp16x2 partials ----
    const unsigned FULL = 0xffffffffu;
    #pragma unroll
    for (int t = 0; t < 2; t++) {
        float l0 = l[t][0], l1 = l[t][1];
        l0 += __shfl_xor_sync(FULL, l0, 1); l0 += __shfl_xor_sync(FULL, l0, 2);
        l1 += __shfl_xor_sync(FULL, l1, 1); l1 += __shfl_xor_sync(FULL, l1, 2);

        const int q0 = qbase + t * 16 + gid;
        const int q1 = q0 + 8;
        const int prow0 = ((h * S) + q0) * KSPLIT + kc;
        const int prow1 = ((h * S) + q1) * KSPLIT + kc;
        if (tig == 0) { g_pl[prow0] = l0; g_pl[prow1] = l1; }

        uint32_t* po0 = g_po + (size_t)prow0 * 16;
        uint32_t* po1 = g_po + (size_t)prow1 * 16;
        #pragma unroll
        for (int nc = 0; nc < 4; nc++) {
            po0[nc * 4 + tig] = pack_h2(o[t][nc][0], o[t][nc][1]);   // d = 8nc+2tig, +1
            po1[nc * 4 + tig] = pack_h2(o[t][nc][2], o[t][nc][3]);
        }
    }
}

// ---------------- kernel 3: combine split-K + sum-pool over j (fp16 in) -----
// grid (64, H); 128 threads: jg = tid>>4 (8 j-groups), dp = tid&15 (d-pair).
__global__ __launch_bounds__(128) void reduce_kernel(float* __restrict__ out) {
    const int i = blockIdx.x;
    const int h = blockIdx.y;
    const int tid = threadIdx.x;
    const int jg = tid >> 4;
    const int dp = tid & 15;

    __shared__ float sinvL[64];
    __shared__ float2 sacc[128];

    if (tid < 64) {
        int s = i * 64 + tid;
        int base = (h * S + s) * KSPLIT;
        float L = 0.0f;
        #pragma unroll
        for (int k = 0; k < KSPLIT; k++) L += g_pl[base + k];
        sinvL[tid] = 1.0f / L;
    }
    __syncthreads();

    float2 acc = make_float2(0.f, 0.f);
    #pragma unroll
    for (int jj = 0; jj < 8; jj++) {
        int j = jg * 8 + jj;
        int s = i * 64 + j;
        size_t base = ((size_t)(h * S + s) * KSPLIT) * 16 + dp;
        float2 ov = make_float2(0.f, 0.f);
        #pragma unroll
        for (int k = 0; k < KSPLIT; k++) {
            float2 v = unpack_h2(g_po[base + (size_t)k * 16]);
            ov.x += v.x;
            ov.y += v.y;
        }
        float w = sinvL[j];
        acc.x += ov.x * w;
        acc.y += ov.y * w;
    }

    sacc[tid] = acc;
    __syncthreads();
    if (tid < 16) {
        float2 r = make_float2(0.f, 0.f);
        #pragma unroll
        for (int g = 0; g < 8; g++) {
            float2 v = sacc[g * 16 + tid];
            r.x += v.x;
            r.y += v.y;
        }
        *(float2*)(out + i * HD + h * 32 + 2 * tid) = r;
    }
}

// ---------------- launch ----------------------------------------------------
extern "C" void kernel_launch(void* const* d_in, const int* in_sizes, int n_in,
                              void* d_out, int out_size) {
    const float* x    = (const float*)d_in[0];
    const int*   mask = (const int*)  d_in[1];
    const float* Wq   = (const float*)d_in[2];
    const float* bq   = (const float*)d_in[3];
    const float* Wk   = (const float*)d_in[4];
    const float* bk   = (const float*)d_in[5];
    const float* Wv   = (const float*)d_in[6];
    const float* bv   = (const float*)d_in[7];
    float* out = (float*)d_out;

    prep_kernel<<<304, 256>>>(x, Wq, Wk, Wv);
    proj_kernel<<<dim3(S / 64, 3), 256>>>(bq, bk, bv);
    attn_kernel<<<dim3(S / QT, H, KSPLIT), 256>>>(mask);
    reduce_kernel<<<dim3(64, H), 128>>>(out);
}

// round 15
// speedup vs baseline: 1.0056x; 1.0056x over previous
#include <cuda_runtime.h>
#include <cuda_fp16.h>
#include <cstdint>

#define S        4096
#define D_IN     128
#define H        4
#define D        32
#define HD       128
#define KSPLIT   4
#define KEYS_PER_SPLIT (S / KSPLIT)   // 1024
#define KT       128                   // keys per smem tile
#define QT       256                   // queries per attention block (8 warps * 32)
#define NEGBIG   1e30f
#define QSCALE   (0.17677669529663687f * 1.4426950408889634f)  // scale*log2e

#define V_CHSTR  264                   // dwords per 16-key V chunk (256 + 8 pad)

// ---------------- scratch (fp16x2 packed) ------------------------------------
__device__ uint32_t g_q[H * S * 16];        // permuted cols, pre-scaled by QSCALE
__device__ uint32_t g_k[H * S * 16];        // permuted cols
__device__ uint32_t g_v[H * S * 16];        // plain d-pair packing
__device__ uint32_t g_xf[S * 64];           // x packed, A-fragment order
__device__ uint32_t g_wt[3 * 128 * 64];     // W^T packed, swizzled smem image
__device__ float g_pl[H * S * KSPLIT];
__device__ uint32_t g_po[H * S * KSPLIT * 16];   // fp16x2 partial outputs (d-pairs)

// ---------------- helpers ----------------------------------------------------
__device__ __forceinline__ float ex2(float x) {
    float r;
    asm("ex2.approx.f32 %0, %1;" : "=f"(r) : "f"(x));
    return r;
}
__device__ __forceinline__ uint32_t pack_h2(float lo, float hi) {
    __half2 h = __floats2half2_rn(lo, hi);       // x = lo bits, y = hi bits
    return *reinterpret_cast<uint32_t*>(&h);
}
__device__ __forceinline__ float2 unpack_h2(uint32_t u) {
    __half2 h = *reinterpret_cast<__half2*>(&u);
    return __half22float2(h);
}
__device__ __forceinline__ void mma16(float* d,
                                      uint32_t a0, uint32_t a1, uint32_t a2, uint32_t a3,
                                      uint32_t b0, uint32_t b1) {
    asm("mma.sync.aligned.m16n8k16.row.col.f32.f16.f16.f32 "
        "{%0,%1,%2,%3}, {%4,%5,%6,%7}, {%8,%9}, {%0,%1,%2,%3};"
        : "+f"(d[0]), "+f"(d[1]), "+f"(d[2]), "+f"(d[3])
        : "r"(a0), "r"(a1), "r"(a2), "r"(a3), "r"(b0), "r"(b1));
}
// group swizzle keyed on row (bit0 -> group bit2; bits1-2 -> group bits0-1)
__device__ __forceinline__ int swz3(int r) { return ((r & 1) << 2) | ((r >> 1) & 3); }

// ---------------- kernel 0: prep (pack x in A-frag order; pack W^T) ----------
// grid 304: blocks 0..255 pack x (4 pairs/thread); 256..303 pack W (2 pairs/thread).
__global__ __launch_bounds__(256) void prep_kernel(
    const float* __restrict__ x,
    const float* __restrict__ Wq, const float* __restrict__ Wk,
    const float* __restrict__ Wv) {
    const int bid = blockIdx.x;
    const int tid = threadIdx.x;
    if (bid < 256) {
        const int base = (bid * 256 + tid) * 4;
        #pragma unroll
        for (int i = 0; i < 4; i++) {
            int e = base + i;                 // pair index 0..262143
            int row = e >> 6, p = e & 63;
            float2 xv = *(const float2*)(x + (size_t)row * D_IN + 2 * p);
            g_xf[row * 64 + ((p & 7) << 3) + (p >> 3)] = pack_h2(xv.x, xv.y);
        }
    } else {
        const int b = bid - 256;              // 0..47
        const int proj = b >> 4, chunk = b & 15;
        const float* W = (proj == 0) ? Wq : (proj == 1) ? Wk : Wv;
        uint32_t* out = g_wt + proj * 8192;
        #pragma unroll
        for (int i = 0; i < 2; i++) {
            int e = chunk * 512 + i * 256 + tid;
            int n = e & 127, p = e >> 7;
            float w0 = W[(size_t)(2 * p) * HD + n];
            float w1 = W[(size_t)(2 * p + 1) * HD + n];
            out[n * 64 + ((((p & 7) ^ swz3(n)) << 3) | (p >> 3))] = pack_h2(w0, w1);
        }
    }
}

// ---------------- kernel 1: fp16 MMA QKV projection (prepped inputs) ---------
// grid (64 row-tiles of 64 rows, 3 proj) = 192 blocks; 256 threads = 8 warps.
__global__ __launch_bounds__(256) void proj_kernel(
    const float* __restrict__ bq, const float* __restrict__ bk,
    const float* __restrict__ bv) {

    __shared__ __align__(16) uint32_t swt[8192];   // 32 KB W^T image
    __shared__ float sb[128];

    const int rowbase = blockIdx.x * 64;
    const int proj = blockIdx.y;
    const float* bias = (proj == 0) ? bq : (proj == 1) ? bk : bv;
    uint32_t* out     = (proj == 0) ? g_q : (proj == 1) ? g_k : g_v;

    const int tid  = threadIdx.x;
    const int wid  = tid >> 5;
    const int lane = tid & 31;
    const int gid  = lane >> 2;
    const int tig  = lane & 3;
    const int nh   = wid >> 2;
    const int rh   = wid & 3;

    {
        const uint4* src = (const uint4*)(g_wt + proj * 8192);
        uint4* dst = (uint4*)swt;
        #pragma unroll
        for (int i = 0; i < 8; i++) dst[tid + i * 256] = src[tid + i * 256];
    }
    if (tid < 128) sb[tid] = bias[tid];

    const int r0 = rowbase + rh * 16 + gid;
    const int r1 = r0 + 8;
    uint32_t a0[8], a1[8], a2[8], a3[8];
    {
        const uint32_t* x0 = g_xf + (size_t)r0 * 64;
        const uint32_t* x1 = g_xf + (size_t)r1 * 64;
        *(uint4*)&a0[0] = *(const uint4*)&x0[tig * 8];
        *(uint4*)&a0[4] = *(const uint4*)&x0[tig * 8 + 4];
        *(uint4*)&a2[0] = *(const uint4*)&x0[(tig + 4) * 8];
        *(uint4*)&a2[4] = *(const uint4*)&x0[(tig + 4) * 8 + 4];
        *(uint4*)&a1[0] = *(const uint4*)&x1[tig * 8];
        *(uint4*)&a1[4] = *(const uint4*)&x1[tig * 8 + 4];
        *(uint4*)&a3[0] = *(const uint4*)&x1[(tig + 4) * 8];
        *(uint4*)&a3[4] = *(const uint4*)&x1[(tig + 4) * 8 + 4];
    }
    __syncthreads();

    const float oscale = (proj == 0) ? QSCALE : 1.0f;
    const bool permute = (proj != 2);

    #pragma unroll 1
    for (int nb2 = 0; nb2 < 4; nb2++) {
        const int nbA = nh * 8 + 2 * nb2, nbB = nbA + 1;
        const int nA = nbA * 8 + gid, nB = nbB * 8 + gid;

        uint32_t b0A[8], b1A[8], b0B[8], b1B[8];
        {
            const uint32_t* wA = &swt[nA * 64];
            int ga = ((tig)     ^ swz3(nA)) << 3;
            int gb = ((tig + 4) ^ swz3(nA)) << 3;
            *(uint4*)&b0A[0] = *(const uint4*)&wA[ga]; *(uint4*)&b0A[4] = *(const uint4*)&wA[ga + 4];
            *(uint4*)&b1A[0] = *(const uint4*)&wA[gb]; *(uint4*)&b1A[4] = *(const uint4*)&wA[gb + 4];
            const uint32_t* wB = &swt[nB * 64];
            int gc = ((tig)     ^ swz3(nB)) << 3;
            int gd = ((tig + 4) ^ swz3(nB)) << 3;
            *(uint4*)&b0B[0] = *(const uint4*)&wB[gc]; *(uint4*)&b0B[4] = *(const uint4*)&wB[gc + 4];
            *(uint4*)&b1B[0] = *(const uint4*)&wB[gd]; *(uint4*)&b1B[4] = *(const uint4*)&wB[gd + 4];
        }

        float cA[4] = {0.f, 0.f, 0.f, 0.f};
        float cB[4] = {0.f, 0.f, 0.f, 0.f};
        #pragma unroll
        for (int ks = 0; ks < 8; ks++) {
            mma16(cA, a0[ks], a1[ks], a2[ks], a3[ks], b0A[ks], b1A[ks]);
            mma16(cB, a0[ks], a1[ks], a2[ks], a3[ks], b0B[ks], b1B[ks]);
        }

        #pragma unroll
        for (int s = 0; s < 2; s++) {
            const float* c = s ? cB : cA;
            const int nb = s ? nbB : nbA;
            const int col0 = 8 * nb + 2 * tig;
            float v0 = (c[0] + sb[col0])     * oscale;
            float v1 = (c[1] + sb[col0 + 1]) * oscale;
            float v2 = (c[2] + sb[col0])     * oscale;
            float v3 = (c[3] + sb[col0 + 1]) * oscale;
            int h0 = col0 >> 5;
            int d2 = (col0 >> 1) & 15;
            int p  = permute ? (((d2 & 3) << 2) | (d2 >> 2)) : d2;
            out[((size_t)h0 * S + r0) * 16 + p] = pack_h2(v0, v1);
            out[((size_t)h0 * S + r1) * 16 + p] = pack_h2(v2, v3);
        }
    }
}

// ---------------- kernel 2: fp16 m16n8k16 flash attention -------------------
// grid (16, H, 4) = 256 blocks; 256 threads = 8 warps; 32 queries per warp.
__global__ __launch_bounds__(256, 2) void attn_kernel(const int* __restrict__ mask) {
    const int qtile = blockIdx.x;
    const int h     = blockIdx.y;
    const int kc    = blockIdx.z;
    const int tid   = threadIdx.x;
    const int warp  = tid >> 5;
    const int lane  = tid & 31;
    const int gid   = lane >> 2;
    const int tig   = lane & 3;

    __shared__ __align__(16) uint32_t sk[KT * 16];             // 8 KB (permuted fp16x2)
    __shared__ __align__(16) uint32_t sv[(KT / 16) * V_CHSTR]; // 8.25 KB
    __shared__ float sbias[KT];
    __shared__ int smask[64];

    if (tid < 64) smask[tid] = mask[tid];

    const int qbase = qtile * QT + warp * 32;

    uint4 qlo[2], qhi[2];
    #pragma unroll
    for (int t = 0; t < 2; t++) {
        const uint32_t* qr = g_q + ((size_t)(h * S) + qbase + t * 16 + gid) * 16;
        qlo[t] = *(const uint4*)(qr + 4 * tig);
        qhi[t] = *(const uint4*)(qr + 8 * 16 + 4 * tig);
    }

    float o[2][4][4];
    #pragma unroll
    for (int t = 0; t < 2; t++)
        #pragma unroll
        for (int nc = 0; nc < 4; nc++)
            #pragma unroll
            for (int r = 0; r < 4; r++) o[t][nc][r] = 0.0f;
    float l[2][2] = {{0.f, 0.f}, {0.f, 0.f}};

    const int kbase = kc * KEYS_PER_SPLIT;
    const float2* sb2 = (const float2*)sbias;

    const int vkey2 = tid & 63;
    const int vdb   = tid >> 6;
    const int vch   = vkey2 >> 3;
    const int vkc2  = vkey2 & 7;
    const int vwoff = vch * V_CHSTR + 64 * vdb + 2 * (vkc2 & 3) + (vkc2 >> 2);

    for (int jt = 0; jt < KEYS_PER_SPLIT / KT; jt++) {   // 8 tiles
        __syncthreads();
        {
            const uint4* kg4 = (const uint4*)(g_k + ((size_t)(h * S) + kbase + jt * KT) * 16);
            ((uint4*)sk)[tid]       = kg4[tid];
            ((uint4*)sk)[tid + 256] = kg4[tid + 256];

            const uint4* vg4 = (const uint4*)(g_v + ((size_t)(h * S) + kbase + jt * KT) * 16);
            uint4 e4 = vg4[(2 * vkey2) * 4 + vdb];
            uint4 o4 = vg4[(2 * vkey2) * 4 + 4 + vdb];
            uint32_t* dst = &sv[vwoff];
            dst[0]  = __byte_perm(e4.x, o4.x, 0x5410);
            dst[8]  = __byte_perm(e4.x, o4.x, 0x7632);
            dst[16] = __byte_perm(e4.y, o4.y, 0x5410);
            dst[24] = __byte_perm(e4.y, o4.y, 0x7632);
            dst[32] = __byte_perm(e4.z, o4.z, 0x5410);
            dst[40] = __byte_perm(e4.z, o4.z, 0x7632);
            dst[48] = __byte_perm(e4.w, o4.w, 0x5410);
            dst[56] = __byte_perm(e4.w, o4.w, 0x7632);

            if (tid < KT) {
                int key = kbase + jt * KT + tid;
                sbias[tid] = (smask[key >> 6] && smask[key & 63]) ? 0.0f : -NEGBIG;
            }
        }
        __syncthreads();

        #pragma unroll 1
        for (int kg = 0; kg < KT / 16; kg++) {     // 8 chunks of 16 keys
            const uint4 kb0 = *(const uint4*)&sk[(kg * 16 + gid) * 16 + 4 * tig];
            const uint4 kb1 = *(const uint4*)&sk[(kg * 16 + 8 + gid) * 16 + 4 * tig];

            float c[2][2][4];
            #pragma unroll
            for (int t = 0; t < 2; t++) {
                #pragma unroll
                for (int g = 0; g < 2; g++)
                    c[t][g][0] = c[t][g][1] = c[t][g][2] = c[t][g][3] = 0.0f;
                mma16(c[t][0], qlo[t].x, qhi[t].x, qlo[t].y, qhi[t].y, kb0.x, kb0.y);
                mma16(c[t][0], qlo[t].z, qhi[t].z, qlo[t].w, qhi[t].w, kb0.z, kb0.w);
                mma16(c[t][1], qlo[t].x, qhi[t].x, qlo[t].y, qhi[t].y, kb1.x, kb1.y);
                mma16(c[t][1], qlo[t].z, qhi[t].z, qlo[t].w, qhi[t].w, kb1.z, kb1.w);
            }

            float2 bg0 = sb2[kg * 8 + tig];
            float2 bg1 = sb2[kg * 8 + 4 + tig];

            uint32_t pa[2][4];
            #pragma unroll
            for (int t = 0; t < 2; t++) {
                float p00 = ex2(c[t][0][0] + bg0.x), p01 = ex2(c[t][0][1] + bg0.y);
                float p02 = ex2(c[t][0][2] + bg0.x), p03 = ex2(c[t][0][3] + bg0.y);
                float p10 = ex2(c[t][1][0] + bg1.x), p11 = ex2(c[t][1][1] + bg1.y);
                float p12 = ex2(c[t][1][2] + bg1.x), p13 = ex2(c[t][1][3] + bg1.y);
                l[t][0] += (p00 + p01) + (p10 + p11);
                l[t][1] += (p02 + p03) + (p12 + p13);
                pa[t][0] = pack_h2(p00, p01);
                pa[t][1] = pack_h2(p02, p03);
                pa[t][2] = pack_h2(p10, p11);
                pa[t][3] = pack_h2(p12, p13);
            }

            const uint32_t* vb = &sv[kg * V_CHSTR + 8 * gid + 2 * tig];
            #pragma unroll
            for (int nc = 0; nc < 4; nc++) {
                uint2 vv = *(const uint2*)(vb + 64 * nc);
                mma16(o[0][nc], pa[0][0], pa[0][1], pa[0][2], pa[0][3], vv.x, vv.y);
                mma16(o[1][nc], pa[1][0], pa[1][1], pa[1][2], pa[1][3], vv.x, vv.y);
            }
        }
    }

    // ---- reduce l within groups; write fp16x2 partials ----
    const unsigned FULL = 0xffffffffu;
    #pragma unroll
    for (int t = 0; t < 2; t++) {
        float l0 = l[t][0], l1 = l[t][1];
        l0 += __shfl_xor_sync(FULL, l0, 1); l0 += __shfl_xor_sync(FULL, l0, 2);
        l1 += __shfl_xor_sync(FULL, l1, 1); l1 += __shfl_xor_sync(FULL, l1, 2);

        const int q0 = qbase + t * 16 + gid;
        const int q1 = q0 + 8;
        const int prow0 = ((h * S) + q0) * KSPLIT + kc;
        const int prow1 = ((h * S) + q1) * KSPLIT + kc;
        if (tig == 0) { g_pl[prow0] = l0; g_pl[prow1] = l1; }

        uint32_t* po0 = g_po + (size_t)prow0 * 16;
        uint32_t* po1 = g_po + (size_t)prow1 * 16;
        #pragma unroll
        for (int nc = 0; nc < 4; nc++) {
            po0[nc * 4 + tig] = pack_h2(o[t][nc][0], o[t][nc][1]);   // d = 8nc+2tig, +1
            po1[nc * 4 + tig] = pack_h2(o[t][nc][2], o[t][nc][3]);
        }
    }
}

// ---------------- kernel 3: combine split-K + sum-pool over j (fp16 in) -----
// grid (64, H); 512 threads: jg = tid>>4 (32 j-groups of 2 j), dp = tid&15.
__global__ __launch_bounds__(512) void reduce_kernel(float* __restrict__ out) {
    const int i = blockIdx.x;
    const int h = blockIdx.y;
    const int tid = threadIdx.x;
    const int jg = tid >> 4;
    const int dp = tid & 15;

    __shared__ float sinvL[64];
    __shared__ float2 sacc[512];

    if (tid < 64) {
        int s = i * 64 + tid;
        int base = (h * S + s) * KSPLIT;
        float L = 0.0f;
        #pragma unroll
        for (int k = 0; k < KSPLIT; k++) L += g_pl[base + k];
        sinvL[tid] = 1.0f / L;
    }
    __syncthreads();

    float2 acc = make_float2(0.f, 0.f);
    #pragma unroll
    for (int jj = 0; jj < 2; jj++) {
        int j = jg * 2 + jj;
        int s = i * 64 + j;
        size_t base = ((size_t)(h * S + s) * KSPLIT) * 16 + dp;
        float2 ov = make_float2(0.f, 0.f);
        #pragma unroll
        for (int k = 0; k < KSPLIT; k++) {
            float2 v = unpack_h2(g_po[base + (size_t)k * 16]);
            ov.x += v.x;
            ov.y += v.y;
        }
        float w = sinvL[j];
        acc.x += ov.x * w;
        acc.y += ov.y * w;
    }

    sacc[tid] = acc;
    __syncthreads();
    // stage 1: 128 threads fold 32 j-groups -> 8 partials per d-pair
    if (tid < 128) {
        const int g4 = tid >> 4;        // 0..7
        const int dq = tid & 15;
        float2 r = make_float2(0.f, 0.f);
        #pragma unroll
        for (int m = 0; m < 4; m++) {
            float2 v = sacc[(g4 * 4 + m) * 16 + dq];
            r.x += v.x;
            r.y += v.y;
        }
        sacc[tid] = r;
    }
    __syncthreads();
    if (tid < 16) {
        float2 r = make_float2(0.f, 0.f);
        #pragma unroll
        for (int g = 0; g < 8; g++) {
            float2 v = sacc[g * 16 + tid];
            r.x += v.x;
            r.y += v.y;
        }
        *(float2*)(out + i * HD + h * 32 + 2 * tid) = r;
    }
}

// ---------------- launch ----------------------------------------------------
extern "C" void kernel_launch(void* const* d_in, const int* in_sizes, int n_in,
                              void* d_out, int out_size) {
    const float* x    = (const float*)d_in[0];
    const int*   mask = (const int*)  d_in[1];
    const float* Wq   = (const float*)d_in[2];
    const float* bq   = (const float*)d_in[3];
    const float* Wk   = (const float*)d_in[4];
    const float* bk   = (const float*)d_in[5];
    const float* Wv   = (const float*)d_in[6];
    const float* bv   = (const float*)d_in[7];
    float* out = (float*)d_out;

    prep_kernel<<<304, 256>>>(x, Wq, Wk, Wv);
    proj_kernel<<<dim3(S / 64, 3), 256>>>(bq, bk, bv);
    attn_kernel<<<dim3(S / QT, H, KSPLIT), 256>>>(mask);
    reduce_kernel<<<dim3(64, H), 512>>>(out);
}